// round 1
// baseline (speedup 1.0000x reference)
#include <cuda_runtime.h>
#include <math.h>

#define B_   8
#define S_   2048
#define D_   1024
#define DFF_ 4096
#define M_   (B_ * S_)   // 16384 rows

#define BM 128
#define BN 128
#define BK 16
#define TM 8
#define TN 8
// 256 threads = 16x16 thread grid, each computes 8x8 microtile

// ---------------- scratch (device globals; no allocation allowed) ----------------
__device__ float g_q[(size_t)M_ * D_];           // 64 MB
__device__ float g_k[(size_t)M_ * D_];           // 64 MB
__device__ float g_v[(size_t)M_ * D_];           // 64 MB
__device__ float g_scores[(size_t)B_ * S_ * S_]; // 134 MB
__device__ float g_attn[(size_t)M_ * D_];        // 64 MB
__device__ float g_h[(size_t)M_ * DFF_];         // 256 MB

// ---------------- generic C = A(MxK) * W(NxK)^T + bias, optional GELU -------------
// act: 0 = none, 1 = exact GELU
__global__ __launch_bounds__(256) void gemm_nt_bias(
    const float* __restrict__ A, const float* __restrict__ W,
    const float* __restrict__ bias, float* __restrict__ C,
    int M, int N, int K, int act)
{
    __shared__ float As[BK][BM];
    __shared__ float Ws[BK][BN];

    const int bm = blockIdx.y, bn = blockIdx.x;
    const int tid = threadIdx.x;
    const int tr = tid >> 4;          // 0..15
    const int tc = tid & 15;          // 0..15

    const float* Ab = A + (size_t)bm * BM * K;
    const float* Wb = W + (size_t)bn * BN * K;

    float acc[TM][TN];
#pragma unroll
    for (int i = 0; i < TM; i++)
#pragma unroll
        for (int j = 0; j < TN; j++) acc[i][j] = 0.f;

    for (int k0 = 0; k0 < K; k0 += BK) {
#pragma unroll
        for (int l = 0; l < 2; l++) {
            int idx = tid + l * 256;          // float4 id 0..511
            int row = idx >> 2;               // 0..127
            int c4  = (idx & 3) * 4;          // 0,4,8,12
            float4 a = *(const float4*)(Ab + (size_t)row * K + k0 + c4);
            As[c4 + 0][row] = a.x; As[c4 + 1][row] = a.y;
            As[c4 + 2][row] = a.z; As[c4 + 3][row] = a.w;
            float4 w = *(const float4*)(Wb + (size_t)row * K + k0 + c4);
            Ws[c4 + 0][row] = w.x; Ws[c4 + 1][row] = w.y;
            Ws[c4 + 2][row] = w.z; Ws[c4 + 3][row] = w.w;
        }
        __syncthreads();
#pragma unroll
        for (int kk = 0; kk < BK; kk++) {
            float4 a0 = *(const float4*)&As[kk][tr * TM];
            float4 a1 = *(const float4*)&As[kk][tr * TM + 4];
            float4 w0 = *(const float4*)&Ws[kk][tc * TN];
            float4 w1 = *(const float4*)&Ws[kk][tc * TN + 4];
            float af[TM] = {a0.x, a0.y, a0.z, a0.w, a1.x, a1.y, a1.z, a1.w};
            float wf[TN] = {w0.x, w0.y, w0.z, w0.w, w1.x, w1.y, w1.z, w1.w};
#pragma unroll
            for (int i = 0; i < TM; i++)
#pragma unroll
                for (int j = 0; j < TN; j++)
                    acc[i][j] = fmaf(af[i], wf[j], acc[i][j]);
        }
        __syncthreads();
    }

    const float* bptr = bias + (size_t)bn * BN;
#pragma unroll
    for (int i = 0; i < TM; i++) {
        size_t m = (size_t)bm * BM + tr * TM + i;
        float* crow = C + m * N + (size_t)bn * BN;
#pragma unroll
        for (int j = 0; j < TN; j += 4) {
            float4 o;
            float* op = &o.x;
#pragma unroll
            for (int t = 0; t < 4; t++) {
                float v = acc[i][j + t] + bptr[tc * TN + j + t];
                if (act == 1) v = 0.5f * v * (1.0f + erff(v * 0.70710678118654752f));
                op[t] = v;
            }
            *(float4*)(crow + tc * TN + j) = o;
        }
    }
}

// ---------------- scores = scale * q k^T, batched, causal block skip ----------------
__global__ __launch_bounds__(256) void scores_nt(
    const float* __restrict__ Q, const float* __restrict__ Kb,
    float* __restrict__ SC)
{
    const int bm = blockIdx.y, bn = blockIdx.x;
    if (bn > bm) return;                      // block entirely above diagonal
    const int b = blockIdx.z;

    __shared__ float As[BK][BM];
    __shared__ float Ws[BK][BN];

    const int tid = threadIdx.x;
    const int tr = tid >> 4, tc = tid & 15;

    const float* Ab = Q  + (size_t)b * S_ * D_ + (size_t)bm * BM * D_;
    const float* Wb = Kb + (size_t)b * S_ * D_ + (size_t)bn * BN * D_;

    float acc[TM][TN];
#pragma unroll
    for (int i = 0; i < TM; i++)
#pragma unroll
        for (int j = 0; j < TN; j++) acc[i][j] = 0.f;

    for (int k0 = 0; k0 < D_; k0 += BK) {
#pragma unroll
        for (int l = 0; l < 2; l++) {
            int idx = tid + l * 256;
            int row = idx >> 2;
            int c4  = (idx & 3) * 4;
            float4 a = *(const float4*)(Ab + (size_t)row * D_ + k0 + c4);
            As[c4 + 0][row] = a.x; As[c4 + 1][row] = a.y;
            As[c4 + 2][row] = a.z; As[c4 + 3][row] = a.w;
            float4 w = *(const float4*)(Wb + (size_t)row * D_ + k0 + c4);
            Ws[c4 + 0][row] = w.x; Ws[c4 + 1][row] = w.y;
            Ws[c4 + 2][row] = w.z; Ws[c4 + 3][row] = w.w;
        }
        __syncthreads();
#pragma unroll
        for (int kk = 0; kk < BK; kk++) {
            float4 a0 = *(const float4*)&As[kk][tr * TM];
            float4 a1 = *(const float4*)&As[kk][tr * TM + 4];
            float4 w0 = *(const float4*)&Ws[kk][tc * TN];
            float4 w1 = *(const float4*)&Ws[kk][tc * TN + 4];
            float af[TM] = {a0.x, a0.y, a0.z, a0.w, a1.x, a1.y, a1.z, a1.w};
            float wf[TN] = {w0.x, w0.y, w0.z, w0.w, w1.x, w1.y, w1.z, w1.w};
#pragma unroll
            for (int i = 0; i < TM; i++)
#pragma unroll
                for (int j = 0; j < TN; j++)
                    acc[i][j] = fmaf(af[i], wf[j], acc[i][j]);
        }
        __syncthreads();
    }

    const float scale = 0.03125f;  // 1/sqrt(1024)
    float* Cb = SC + (size_t)b * S_ * S_;
#pragma unroll
    for (int i = 0; i < TM; i++) {
        size_t m = (size_t)bm * BM + tr * TM + i;
        float* crow = Cb + m * S_ + (size_t)bn * BN;
#pragma unroll
        for (int j = 0; j < TN; j += 4) {
            float4 o;
            o.x = acc[i][j + 0] * scale;
            o.y = acc[i][j + 1] * scale;
            o.z = acc[i][j + 2] * scale;
            o.w = acc[i][j + 3] * scale;
            *(float4*)(crow + tc * TN + j) = o;
        }
    }
}

// ---------------- causal row softmax (in place), zero the masked tail ----------------
__global__ __launch_bounds__(256) void softmax_causal(float* __restrict__ SC)
{
    const int q = blockIdx.x;
    const int b = blockIdx.y;
    float* row = SC + ((size_t)b * S_ + q) * S_;
    const int n = q + 1;
    const int tid = threadIdx.x;
    __shared__ float red[256];

    float m = -INFINITY;
    for (int i = tid; i < n; i += 256) m = fmaxf(m, row[i]);
    red[tid] = m; __syncthreads();
    for (int s = 128; s > 0; s >>= 1) {
        if (tid < s) red[tid] = fmaxf(red[tid], red[tid + s]);
        __syncthreads();
    }
    m = red[0]; __syncthreads();

    float sum = 0.f;
    for (int i = tid; i < n; i += 256) {
        float e = __expf(row[i] - m);
        row[i] = e;
        sum += e;
    }
    red[tid] = sum; __syncthreads();
    for (int s = 128; s > 0; s >>= 1) {
        if (tid < s) red[tid] += red[tid + s];
        __syncthreads();
    }
    const float inv = 1.0f / red[0];
    for (int i = tid; i < n; i += 256) row[i] *= inv;
    for (int i = n + tid; i < S_; i += 256) row[i] = 0.f;  // zero masked tail for PV
}

// ---------------- attn_out = P @ V, batched NN, causal K bound ----------------
__global__ __launch_bounds__(256) void pv_nn(
    const float* __restrict__ P, const float* __restrict__ V,
    float* __restrict__ O)
{
    const int bm = blockIdx.y, bn = blockIdx.x, b = blockIdx.z;

    __shared__ float As[BK][BM];
    __shared__ float Bs[BK][BN];

    const int tid = threadIdx.x;
    const int tr = tid >> 4, tc = tid & 15;

    const float* Ab = P + (size_t)b * S_ * S_ + (size_t)bm * BM * S_;
    const float* Vb = V + (size_t)b * S_ * D_;

    float acc[TM][TN];
#pragma unroll
    for (int i = 0; i < TM; i++)
#pragma unroll
        for (int j = 0; j < TN; j++) acc[i][j] = 0.f;

    const int Kmax = (bm + 1) * BM;   // keys beyond the diagonal block are zero

    for (int k0 = 0; k0 < Kmax; k0 += BK) {
        // A tile (P rows)
#pragma unroll
        for (int l = 0; l < 2; l++) {
            int idx = tid + l * 256;
            int row = idx >> 2;
            int c4  = (idx & 3) * 4;
            float4 a = *(const float4*)(Ab + (size_t)row * S_ + k0 + c4);
            As[c4 + 0][row] = a.x; As[c4 + 1][row] = a.y;
            As[c4 + 2][row] = a.z; As[c4 + 3][row] = a.w;
        }
        // B tile (V rows k0..k0+15, cols bn*128..+127)
#pragma unroll
        for (int l = 0; l < 2; l++) {
            int idx = tid + l * 256;          // 0..511
            int row = idx >> 5;               // 0..15
            int c4  = (idx & 31) * 4;         // 0..124
            float4 v4 = *(const float4*)(Vb + (size_t)(k0 + row) * D_ + (size_t)bn * BN + c4);
            *(float4*)&Bs[row][c4] = v4;
        }
        __syncthreads();
#pragma unroll
        for (int kk = 0; kk < BK; kk++) {
            float4 a0 = *(const float4*)&As[kk][tr * TM];
            float4 a1 = *(const float4*)&As[kk][tr * TM + 4];
            float4 w0 = *(const float4*)&Bs[kk][tc * TN];
            float4 w1 = *(const float4*)&Bs[kk][tc * TN + 4];
            float af[TM] = {a0.x, a0.y, a0.z, a0.w, a1.x, a1.y, a1.z, a1.w};
            float wf[TN] = {w0.x, w0.y, w0.z, w0.w, w1.x, w1.y, w1.z, w1.w};
#pragma unroll
            for (int i = 0; i < TM; i++)
#pragma unroll
                for (int j = 0; j < TN; j++)
                    acc[i][j] = fmaf(af[i], wf[j], acc[i][j]);
        }
        __syncthreads();
    }

    float* Ob = O + (size_t)b * S_ * D_;
#pragma unroll
    for (int i = 0; i < TM; i++) {
        size_t m = (size_t)bm * BM + tr * TM + i;
        float* crow = Ob + m * D_ + (size_t)bn * BN;
#pragma unroll
        for (int j = 0; j < TN; j += 4) {
            float4 o;
            o.x = acc[i][j + 0];
            o.y = acc[i][j + 1];
            o.z = acc[i][j + 2];
            o.w = acc[i][j + 3];
            *(float4*)(crow + tc * TN + j) = o;
        }
    }
}

// ---------------- launch ----------------
extern "C" void kernel_launch(void* const* d_in, const int* in_sizes, int n_in,
                              void* d_out, int out_size)
{
    const float* x  = (const float*)d_in[0];
    const float* Wq = (const float*)d_in[1];
    const float* bq = (const float*)d_in[2];
    const float* Wk = (const float*)d_in[3];
    const float* bk = (const float*)d_in[4];
    const float* Wv = (const float*)d_in[5];
    const float* bv = (const float*)d_in[6];
    const float* W1 = (const float*)d_in[7];
    const float* b1 = (const float*)d_in[8];
    const float* W2 = (const float*)d_in[9];
    const float* b2 = (const float*)d_in[10];
    float* out = (float*)d_out;

    float *q, *k, *v, *sc, *ao, *h;
    cudaGetSymbolAddress((void**)&q,  g_q);
    cudaGetSymbolAddress((void**)&k,  g_k);
    cudaGetSymbolAddress((void**)&v,  g_v);
    cudaGetSymbolAddress((void**)&sc, g_scores);
    cudaGetSymbolAddress((void**)&ao, g_attn);
    cudaGetSymbolAddress((void**)&h,  g_h);

    // QKV projections: (16384 x 1024) @ (1024 x 1024)^T
    dim3 gq(D_ / BN, M_ / BM);
    gemm_nt_bias<<<gq, 256>>>(x, Wq, bq, q, M_, D_, D_, 0);
    gemm_nt_bias<<<gq, 256>>>(x, Wk, bk, k, M_, D_, D_, 0);
    gemm_nt_bias<<<gq, 256>>>(x, Wv, bv, v, M_, D_, D_, 0);

    // scores = scale * q k^T (causal blocks only)
    scores_nt<<<dim3(S_ / BN, S_ / BM, B_), 256>>>(q, k, sc);

    // causal softmax
    softmax_causal<<<dim3(S_, B_), 256>>>(sc);

    // attn_out = P @ V
    pv_nn<<<dim3(D_ / BN, S_ / BM, B_), 256>>>(sc, v, ao);

    // MLP
    gemm_nt_bias<<<dim3(DFF_ / BN, M_ / BM), 256>>>(ao, W1, b1, h, M_, DFF_, D_, 1);
    gemm_nt_bias<<<dim3(D_ / BN, M_ / BM), 256>>>(h, W2, b2, out, M_, D_, DFF_, 0);
}

// round 3
// speedup vs baseline: 2.8698x; 2.8698x over previous
#include <cuda_runtime.h>
#include <cuda_bf16.h>
#include <math.h>

typedef unsigned int u32;
typedef unsigned long long u64;
typedef __nv_bfloat16 bf16;

#define B_   8
#define S_   2048
#define D_   1024
#define DFF_ 4096
#define M_   (B_*S_)

// ---------------- scratch (device globals) ----------------
__device__ bf16 g_xh[(size_t)M_*D_],  g_xl[(size_t)M_*D_];
__device__ bf16 g_Wqh[(size_t)D_*D_], g_Wql[(size_t)D_*D_];
__device__ bf16 g_Wkh[(size_t)D_*D_], g_Wkl[(size_t)D_*D_];
__device__ bf16 g_Wvh[(size_t)D_*D_], g_Wvl[(size_t)D_*D_];
__device__ bf16 g_W1h[(size_t)DFF_*D_], g_W1l[(size_t)DFF_*D_];
__device__ bf16 g_W2h[(size_t)D_*DFF_], g_W2l[(size_t)D_*DFF_];
__device__ bf16 g_qh[(size_t)M_*D_],  g_ql[(size_t)M_*D_];
__device__ bf16 g_kh[(size_t)M_*D_],  g_kl[(size_t)M_*D_];
__device__ float g_v[(size_t)M_*D_];
__device__ bf16 g_vth[(size_t)B_*D_*S_], g_vtl[(size_t)B_*D_*S_];
__device__ float g_sc[(size_t)B_*S_*S_];
__device__ bf16 g_Ph[(size_t)B_*S_*S_], g_Pl[(size_t)B_*S_*S_];
__device__ bf16 g_aoh[(size_t)M_*D_], g_aol[(size_t)M_*D_];
__device__ bf16 g_hh[(size_t)M_*DFF_], g_hl[(size_t)M_*DFF_];

// ---------------- helpers ----------------
__device__ __forceinline__ u32 smem_u32(const void* p){
    u32 a;
    asm("{ .reg .u64 t; cvta.to.shared.u64 t, %1; cvt.u32.u64 %0, t; }" : "=r"(a) : "l"(p));
    return a;
}
__device__ __forceinline__ u32 pk(bf16 a, bf16 b){
    unsigned short ua = *(unsigned short*)&a, ub = *(unsigned short*)&b;
    return (u32)ua | ((u32)ub << 16);
}
// 16B-chunk XOR swizzle: row-of-64B tile, 4 chunks/row; conflict-free for ldmatrix
__device__ __forceinline__ u32 swz(int row, int ch){
    return (u32)((row*4 + (ch ^ ((row>>1)&3))) * 16);
}

#define CP16(dst, src) asm volatile("cp.async.ca.shared.global [%0], [%1], 16;" :: "r"(dst), "l"(src) : "memory")
#define CP_COMMIT()    asm volatile("cp.async.commit_group;" ::: "memory")
#define CP_WAIT1()     asm volatile("cp.async.wait_group 1;" ::: "memory")
#define CP_WAIT0()     asm volatile("cp.async.wait_group 0;" ::: "memory")

#define LDSM4(r, addr) asm volatile( \
    "ldmatrix.sync.aligned.m8n8.x4.shared.b16 {%0,%1,%2,%3}, [%4];" \
    : "=r"((r)[0]),"=r"((r)[1]),"=r"((r)[2]),"=r"((r)[3]) : "r"(addr))

#define MMA(c, a, b0, b1) asm volatile( \
    "mma.sync.aligned.m16n8k16.row.col.f32.bf16.bf16.f32 " \
    "{%0,%1,%2,%3},{%4,%5,%6,%7},{%8,%9},{%0,%1,%2,%3};" \
    : "+f"((c)[0]),"+f"((c)[1]),"+f"((c)[2]),"+f"((c)[3]) \
    : "r"((a)[0]),"r"((a)[1]),"r"((a)[2]),"r"((a)[3]),"r"(b0),"r"(b1))

#define TILE_B  8192       // 128 rows x 32 bf16 (64B/row)
#define STAGE_B 32768      // 4 tiles per stage
#define SMEM_SZ 65536      // 2 stages

// ================= bf16x3 tensor-core GEMM =================
// C = act( scale * A[M,K] @ B[N,K]^T + bias ), A/B given as hi/lo bf16 pairs.
// Optional fp32 output C and/or split bf16 outputs Ch/Cl.
// causal: 0 none, 1 skip bn>bm, 2 K bounded at (bm+1)*128
__global__ __launch_bounds__(256, 2) void gemm_mma(
    const bf16* __restrict__ Ah, const bf16* __restrict__ Al,
    const bf16* __restrict__ Bh, const bf16* __restrict__ Bl,
    const float* __restrict__ bias,
    float* __restrict__ C, bf16* __restrict__ Ch, bf16* __restrict__ Cl,
    int N, int K, long sA, long sB, long sC,
    float scale, int gelu, int causal)
{
    extern __shared__ char smem[];
    const int bm = blockIdx.y, bn = blockIdx.x, bz = blockIdx.z;
    if (causal == 1 && bn > bm) return;

    const int tid = threadIdx.x, lane = tid & 31, warp = tid >> 5;
    const int wm = warp >> 2, wn = warp & 3;   // 2x4 warp grid: 64m x 32n each
    const u32 sb = smem_u32(smem);

    const bf16* Ah_b = Ah + (size_t)bz*sA + (size_t)bm*128*K;
    const bf16* Al_b = Al + (size_t)bz*sA + (size_t)bm*128*K;
    const bf16* Bh_b = Bh + (size_t)bz*sB + (size_t)bn*128*K;
    const bf16* Bl_b = Bl + (size_t)bz*sB + (size_t)bn*128*K;

    const int Keff = (causal == 2) ? (bm + 1)*128 : K;
    const int nc = Keff / 32;

    float acc[4][4][4];
#pragma unroll
    for (int i=0;i<4;i++)
#pragma unroll
        for (int j=0;j<4;j++)
#pragma unroll
            for (int t=0;t<4;t++) acc[i][j][t] = 0.f;

    auto load_stage = [&](int c){
        const int buf = c & 1, k0 = c * 32;
        const u32 base = sb + buf * STAGE_B;
#pragma unroll
        for (int t = 0; t < 2; t++){
            int idx = t*256 + tid;
            int row = idx >> 2, ch = idx & 3;
            u32 d = swz(row, ch);
            size_t go = (size_t)row*K + k0 + ch*8;
            CP16(base + d,           (u64)__cvta_generic_to_global(Ah_b + go));
            CP16(base + TILE_B + d,  (u64)__cvta_generic_to_global(Al_b + go));
            CP16(base + 2*TILE_B + d,(u64)__cvta_generic_to_global(Bh_b + go));
            CP16(base + 3*TILE_B + d,(u64)__cvta_generic_to_global(Bl_b + go));
        }
        CP_COMMIT();
    };

    load_stage(0);
    if (nc > 1) load_stage(1);

    const int arow = wm*64 + (lane & 7) + ((lane >> 3) & 1) * 8;
    const int brow = wn*32 + (lane & 7) + ((lane >> 4) & 1) * 8;

    for (int c = 0; c < nc; c++){
        if (nc - c >= 2) CP_WAIT1(); else CP_WAIT0();
        __syncthreads();

        const u32 tAh = sb + (c & 1) * STAGE_B;
        const u32 tAl = tAh + TILE_B;
        const u32 tBh = tAh + 2*TILE_B;
        const u32 tBl = tAh + 3*TILE_B;

#pragma unroll
        for (int s = 0; s < 2; s++){
            const int ach = 2*s + ((lane >> 4) & 1);
            const int bch = 2*s + ((lane >> 3) & 1);

            u32 ah[4][4], bh[2][4];
#pragma unroll
            for (int mt = 0; mt < 4; mt++) LDSM4(ah[mt], tAh + swz(arow + mt*16, ach));
#pragma unroll
            for (int bt = 0; bt < 2; bt++) LDSM4(bh[bt], tBh + swz(brow + bt*16, bch));
#pragma unroll
            for (int mt = 0; mt < 4; mt++)
#pragma unroll
                for (int nt = 0; nt < 4; nt++)
                    MMA(acc[mt][nt], ah[mt], bh[nt>>1][(nt&1)*2], bh[nt>>1][(nt&1)*2+1]);

            u32 bl[2][4];
#pragma unroll
            for (int bt = 0; bt < 2; bt++) LDSM4(bl[bt], tBl + swz(brow + bt*16, bch));
#pragma unroll
            for (int mt = 0; mt < 4; mt++)
#pragma unroll
                for (int nt = 0; nt < 4; nt++)
                    MMA(acc[mt][nt], ah[mt], bl[nt>>1][(nt&1)*2], bl[nt>>1][(nt&1)*2+1]);

            u32 al[4][4];
#pragma unroll
            for (int mt = 0; mt < 4; mt++) LDSM4(al[mt], tAl + swz(arow + mt*16, ach));
#pragma unroll
            for (int mt = 0; mt < 4; mt++)
#pragma unroll
                for (int nt = 0; nt < 4; nt++)
                    MMA(acc[mt][nt], al[mt], bh[nt>>1][(nt&1)*2], bh[nt>>1][(nt&1)*2+1]);
        }
        __syncthreads();
        if (c + 2 < nc) load_stage(c + 2);
    }

    // ---------------- epilogue ----------------
    const int g = lane >> 2, t4 = lane & 3;
    float* Cz  = C  ? C  + (size_t)bz*sC : (float*)0;
    bf16*  Chz = Ch ? Ch + (size_t)bz*sC : (bf16*)0;
    bf16*  Clz = Cl ? Cl + (size_t)bz*sC : (bf16*)0;
    const int row_base = bm*128 + wm*64;
    const int col_base = bn*128 + wn*32;

#pragma unroll
    for (int mt = 0; mt < 4; mt++)
#pragma unroll
    for (int nt = 0; nt < 4; nt++){
        const int col = col_base + nt*8 + 2*t4;
        float b0 = 0.f, b1 = 0.f;
        if (bias){ b0 = bias[col]; b1 = bias[col+1]; }
#pragma unroll
        for (int h = 0; h < 2; h++){
            const int row = row_base + mt*16 + g + h*8;
            float v0 = acc[mt][nt][h*2+0] * scale + b0;
            float v1 = acc[mt][nt][h*2+1] * scale + b1;
            if (gelu){
                v0 = 0.5f*v0*(1.0f + erff(v0*0.70710678118654752f));
                v1 = 0.5f*v1*(1.0f + erff(v1*0.70710678118654752f));
            }
            const size_t off = (size_t)row*N + col;
            if (Cz) *(float2*)(Cz + off) = make_float2(v0, v1);
            if (Chz){
                bf16 h0 = __float2bfloat16_rn(v0), h1 = __float2bfloat16_rn(v1);
                *(u32*)(Chz + off) = pk(h0, h1);
                *(u32*)(Clz + off) = pk(__float2bfloat16_rn(v0 - __bfloat162float(h0)),
                                        __float2bfloat16_rn(v1 - __bfloat162float(h1)));
            }
        }
    }
}

// ---------------- elementwise fp32 -> (hi,lo) bf16 ----------------
__global__ __launch_bounds__(256) void convert_split(
    const float* __restrict__ src, bf16* __restrict__ h, bf16* __restrict__ l)
{
    size_t i = (size_t)blockIdx.x * 256 + threadIdx.x;   // float4 index
    float4 f = ((const float4*)src)[i];
    bf16 h0 = __float2bfloat16_rn(f.x), h1 = __float2bfloat16_rn(f.y);
    bf16 h2 = __float2bfloat16_rn(f.z), h3 = __float2bfloat16_rn(f.w);
    ((uint2*)h)[i] = make_uint2(pk(h0,h1), pk(h2,h3));
    ((uint2*)l)[i] = make_uint2(
        pk(__float2bfloat16_rn(f.x - __bfloat162float(h0)),
           __float2bfloat16_rn(f.y - __bfloat162float(h1))),
        pk(__float2bfloat16_rn(f.z - __bfloat162float(h2)),
           __float2bfloat16_rn(f.w - __bfloat162float(h3))));
}

// ---------------- V transpose + split: vt[b][d][s] = v[b][s][d] ----------------
__global__ __launch_bounds__(256) void transpose_split(
    const float* __restrict__ V, bf16* __restrict__ VTh, bf16* __restrict__ VTl)
{
    __shared__ float t[32][33];
    const int b = blockIdx.z;
    const int s0 = blockIdx.x*32, d0 = blockIdx.y*32;
    const int tx = threadIdx.x, ty = threadIdx.y;
#pragma unroll
    for (int i = ty; i < 32; i += 8)
        t[i][tx] = V[(size_t)b*S_*D_ + (size_t)(s0+i)*D_ + d0 + tx];
    __syncthreads();
#pragma unroll
    for (int i = ty; i < 32; i += 8){
        float v = t[tx][i];
        bf16 h = __float2bfloat16_rn(v);
        size_t off = (size_t)b*D_*S_ + (size_t)(d0+i)*S_ + s0 + tx;
        VTh[off] = h;
        VTl[off] = __float2bfloat16_rn(v - __bfloat162float(h));
    }
}

// ---------------- causal softmax + split, zero tail to 128-multiple ----------------
__global__ __launch_bounds__(256) void softmax_split(
    const float* __restrict__ SC, bf16* __restrict__ Ph, bf16* __restrict__ Pl)
{
    const int q = blockIdx.x, b = blockIdx.y;
    const float* row = SC + ((size_t)b*S_ + q)*S_;
    const int n = q + 1;
    const int nceil = ((q >> 7) + 1) << 7;
    const int tid = threadIdx.x;
    __shared__ float buf[S_];
    __shared__ float red[256];

    float m = -INFINITY;
    for (int i = tid; i < n; i += 256){ float v = row[i]; buf[i] = v; m = fmaxf(m, v); }
    red[tid] = m; __syncthreads();
    for (int s = 128; s > 0; s >>= 1){
        if (tid < s) red[tid] = fmaxf(red[tid], red[tid+s]);
        __syncthreads();
    }
    m = red[0]; __syncthreads();

    float sum = 0.f;
    for (int i = tid; i < n; i += 256){ float e = __expf(buf[i] - m); buf[i] = e; sum += e; }
    red[tid] = sum; __syncthreads();
    for (int s = 128; s > 0; s >>= 1){
        if (tid < s) red[tid] += red[tid+s];
        __syncthreads();
    }
    const float inv = 1.0f / red[0];

    bf16* ph = Ph + ((size_t)b*S_ + q)*S_;
    bf16* pl = Pl + ((size_t)b*S_ + q)*S_;
    for (int i = tid; i < nceil; i += 256){
        if (i < n){
            float p = buf[i] * inv;
            bf16 h = __float2bfloat16_rn(p);
            ph[i] = h;
            pl[i] = __float2bfloat16_rn(p - __bfloat162float(h));
        } else {
            ph[i] = __float2bfloat16_rn(0.f);
            pl[i] = __float2bfloat16_rn(0.f);
        }
    }
}

// ---------------- launch ----------------
extern "C" void kernel_launch(void* const* d_in, const int* in_sizes, int n_in,
                              void* d_out, int out_size)
{
    const float* x  = (const float*)d_in[0];
    const float* Wq = (const float*)d_in[1];
    const float* bq = (const float*)d_in[2];
    const float* Wk = (const float*)d_in[3];
    const float* bk = (const float*)d_in[4];
    const float* Wv = (const float*)d_in[5];
    const float* bv = (const float*)d_in[6];
    const float* W1 = (const float*)d_in[7];
    const float* b1 = (const float*)d_in[8];
    const float* W2 = (const float*)d_in[9];
    const float* b2 = (const float*)d_in[10];
    float* out = (float*)d_out;

    bf16 *xh,*xl,*Wqh,*Wql,*Wkh,*Wkl,*Wvh,*Wvl,*W1h,*W1l,*W2h,*W2l;
    bf16 *qh,*ql,*kh,*kl,*vth,*vtl,*Ph,*Pl,*aoh,*aol,*hh,*hl;
    float *v,*sc;
    cudaGetSymbolAddress((void**)&xh, g_xh);   cudaGetSymbolAddress((void**)&xl, g_xl);
    cudaGetSymbolAddress((void**)&Wqh,g_Wqh);  cudaGetSymbolAddress((void**)&Wql,g_Wql);
    cudaGetSymbolAddress((void**)&Wkh,g_Wkh);  cudaGetSymbolAddress((void**)&Wkl,g_Wkl);
    cudaGetSymbolAddress((void**)&Wvh,g_Wvh);  cudaGetSymbolAddress((void**)&Wvl,g_Wvl);
    cudaGetSymbolAddress((void**)&W1h,g_W1h);  cudaGetSymbolAddress((void**)&W1l,g_W1l);
    cudaGetSymbolAddress((void**)&W2h,g_W2h);  cudaGetSymbolAddress((void**)&W2l,g_W2l);
    cudaGetSymbolAddress((void**)&qh, g_qh);   cudaGetSymbolAddress((void**)&ql, g_ql);
    cudaGetSymbolAddress((void**)&kh, g_kh);   cudaGetSymbolAddress((void**)&kl, g_kl);
    cudaGetSymbolAddress((void**)&v,  g_v);
    cudaGetSymbolAddress((void**)&vth,g_vth);  cudaGetSymbolAddress((void**)&vtl,g_vtl);
    cudaGetSymbolAddress((void**)&sc, g_sc);
    cudaGetSymbolAddress((void**)&Ph, g_Ph);   cudaGetSymbolAddress((void**)&Pl, g_Pl);
    cudaGetSymbolAddress((void**)&aoh,g_aoh);  cudaGetSymbolAddress((void**)&aol,g_aol);
    cudaGetSymbolAddress((void**)&hh, g_hh);   cudaGetSymbolAddress((void**)&hl, g_hl);

    cudaFuncSetAttribute(gemm_mma, cudaFuncAttributeMaxDynamicSharedMemorySize, SMEM_SZ);

    // preconvert inputs
    convert_split<<<(size_t)M_*D_/1024, 256>>>(x,  xh,  xl);
    convert_split<<<(size_t)D_*D_/1024, 256>>>(Wq, Wqh, Wql);
    convert_split<<<(size_t)D_*D_/1024, 256>>>(Wk, Wkh, Wkl);
    convert_split<<<(size_t)D_*D_/1024, 256>>>(Wv, Wvh, Wvl);
    convert_split<<<(size_t)DFF_*D_/1024, 256>>>(W1, W1h, W1l);
    convert_split<<<(size_t)D_*DFF_/1024, 256>>>(W2, W2h, W2l);

    // QKV projections
    gemm_mma<<<dim3(D_/128, M_/128, 1), 256, SMEM_SZ>>>(
        xh, xl, Wqh, Wql, bq, (float*)0, qh, ql, D_, D_, 0,0,0, 1.f, 0, 0);
    gemm_mma<<<dim3(D_/128, M_/128, 1), 256, SMEM_SZ>>>(
        xh, xl, Wkh, Wkl, bk, (float*)0, kh, kl, D_, D_, 0,0,0, 1.f, 0, 0);
    gemm_mma<<<dim3(D_/128, M_/128, 1), 256, SMEM_SZ>>>(
        xh, xl, Wvh, Wvl, bv, v, (bf16*)0, (bf16*)0, D_, D_, 0,0,0, 1.f, 0, 0);

    transpose_split<<<dim3(S_/32, D_/32, B_), dim3(32, 8)>>>(v, vth, vtl);

    // scores = (1/32) q k^T, causal block skip
    gemm_mma<<<dim3(S_/128, S_/128, B_), 256, SMEM_SZ>>>(
        qh, ql, kh, kl, (const float*)0, sc, (bf16*)0, (bf16*)0,
        S_, D_, (long)S_*D_, (long)S_*D_, (long)S_*S_, 0.03125f, 0, 1);

    softmax_split<<<dim3(S_, B_), 256>>>(sc, Ph, Pl);

    // attn = P @ V^T(vt), K bounded at diagonal
    gemm_mma<<<dim3(D_/128, S_/128, B_), 256, SMEM_SZ>>>(
        Ph, Pl, vth, vtl, (const float*)0, (float*)0, aoh, aol,
        D_, S_, (long)S_*S_, (long)D_*S_, (long)S_*D_, 1.f, 0, 2);

    // MLP
    gemm_mma<<<dim3(DFF_/128, M_/128, 1), 256, SMEM_SZ>>>(
        aoh, aol, W1h, W1l, b1, (float*)0, hh, hl, DFF_, D_, 0,0,0, 1.f, 1, 0);
    gemm_mma<<<dim3(D_/128, M_/128, 1), 256, SMEM_SZ>>>(
        hh, hl, W2h, W2l, b2, out, (bf16*)0, (bf16*)0, D_, DFF_, 0,0,0, 1.f, 0, 0);
}